// round 12
// baseline (speedup 1.0000x reference)
#include <cuda_runtime.h>
#include <cuda_bf16.h>

// out[row, k] = clips[row, k - idx] for k >= idx else 0, idx = int(x[row]*N).
// rows = B*C = 1024, N = 32768, fp32. Streaming-bandwidth kernel.
//
// R12: v8 (256-bit) memory ops + UNROLL=2 (64B per thread) -> grid halves to
// 8192 blocks (lower graph-replay overhead; R4 showed smaller grid = smaller
// wall-kernel gap). Interleaved load/rotate/store per unroll step keeps live
// regs ~16 so launch_bounds(256,6) holds without spills. Loads evict_last
// (read window L2-resident across replays); stores st.cs.

#define BLOCK   256
#define UNROLL  2
#define SEG     (BLOCK * 8 * UNROLL)    // 4096 floats per block

typedef unsigned long long u64;

struct f8 { float v[8]; };

__device__ __forceinline__ u64 evict_last_policy() {
    u64 pol;
    asm("createpolicy.fractional.L2::evict_last.b64 %0, 1.0;" : "=l"(pol));
    return pol;
}
__device__ __forceinline__ f8 ld8(const float* p, u64 pol) {
    f8 r;
    asm("ld.global.nc.L2::cache_hint.v8.f32 {%0,%1,%2,%3,%4,%5,%6,%7}, [%8], %9;"
        : "=f"(r.v[0]), "=f"(r.v[1]), "=f"(r.v[2]), "=f"(r.v[3]),
          "=f"(r.v[4]), "=f"(r.v[5]), "=f"(r.v[6]), "=f"(r.v[7])
        : "l"(p), "l"(pol));
    return r;
}
__device__ __forceinline__ void st8(float* p, const f8& r) {
    asm volatile("st.global.cs.v8.f32 [%0], {%1,%2,%3,%4,%5,%6,%7,%8};"
                 :: "l"(p),
                    "f"(r.v[0]), "f"(r.v[1]), "f"(r.v[2]), "f"(r.v[3]),
                    "f"(r.v[4]), "f"(r.v[5]), "f"(r.v[6]), "f"(r.v[7])
                 : "memory");
}

__global__ void __launch_bounds__(BLOCK, 6)
RollScheduler_63273458204913_kernel(
    const float* __restrict__ x,
    const float* __restrict__ clips,
    float* __restrict__ out,
    int n)
{
    const int row = blockIdx.y;
    // Match jnp: (x * n).astype(int32) — f32 multiply, truncate toward zero.
    const int idx = (int)(x[row] * (float)n);

    const float* __restrict__ src = clips + (size_t)row * (size_t)n;
    float*       __restrict__ dst = out   + (size_t)row * (size_t)n;

    const int k0 = blockIdx.x * SEG;          // block segment start
    const int kT = k0 + threadIdx.x * 8;      // this thread's first 8-chunk
    const int r8 = (8 - (idx & 7)) & 7;       // (k - idx) & 7 for k%8==0

    // ---- all-zero block ----
    if (k0 + SEG <= idx) {
        f8 z;
        #pragma unroll
        for (int j = 0; j < 8; j++) z.v[j] = 0.0f;
        #pragma unroll
        for (int u = 0; u < UNROLL; u++)
            st8(dst + kT + u * (BLOCK * 8), z);
        return;
    }

    const u64 pol = evict_last_policy();

    // ---- fully-valid fast path? (block-uniform) ----
    const bool fast = (k0 - idx - r8 >= 0) &&
                      (r8 == 0 || (k0 + SEG + 8 - idx - r8) <= n);

    if (fast) {
        if (r8 == 0) {
            const float* s = src + (kT - idx);
            #pragma unroll
            for (int u = 0; u < UNROLL; u++)
                st8(dst + kT + u * (BLOCK * 8), ld8(s + u * (BLOCK * 8), pol));
        } else {
            const float* a = src + (kT - idx - r8);   // 32B-aligned
            #define ROTCASE(R)                                              \
                do {                                                        \
                    _Pragma("unroll")                                       \
                    for (int u = 0; u < UNROLL; u++) {                      \
                        const f8 lo = ld8(a + u * (BLOCK * 8), pol);        \
                        const f8 hi = ld8(a + u * (BLOCK * 8) + 8, pol);    \
                        f8 o;                                               \
                        _Pragma("unroll")                                   \
                        for (int j = 0; j < 8; j++)                         \
                            o.v[j] = ((R) + j < 8) ? lo.v[(R) + j]          \
                                                   : hi.v[(R) + j - 8];     \
                        st8(dst + kT + u * (BLOCK * 8), o);                 \
                    }                                                       \
                } while (0)
            switch (r8) {   // block-uniform
                case 1: ROTCASE(1); break;
                case 2: ROTCASE(2); break;
                case 3: ROTCASE(3); break;
                case 4: ROTCASE(4); break;
                case 5: ROTCASE(5); break;
                case 6: ROTCASE(6); break;
                default: ROTCASE(7); break;
            }
            #undef ROTCASE
        }
        return;
    }

    // ---- boundary / edge block: guarded scalar (rare, ~1 block per row) ----
    #pragma unroll
    for (int u = 0; u < UNROLL; u++) {
        const int k = kT + u * (BLOCK * 8);
        if (k >= n) break;
        const int base = k - idx;
        f8 o;
        #pragma unroll
        for (int j = 0; j < 8; j++) {
            const int b = base + j;   // b <= n-1 always (idx >= 0, k+7 < n)
            o.v[j] = (b >= 0) ? __ldg(src + b) : 0.0f;
        }
        st8(dst + k, o);
    }
}

extern "C" void kernel_launch(void* const* d_in, const int* in_sizes, int n_in,
                              void* d_out, int out_size) {
    const float* x     = (const float*)d_in[0];   // (B, C)
    const float* clips = (const float*)d_in[1];   // (B, C, N)
    // d_in[2] = actual — unused in the forward computation.
    float* out = (float*)d_out;

    const int rows = in_sizes[0];                 // B*C = 1024
    const int n    = in_sizes[1] / in_sizes[0];   // N = 32768

    dim3 block(BLOCK);
    dim3 grid((n + SEG - 1) / SEG, rows);         // 8 x 1024 = 8192 blocks
    RollScheduler_63273458204913_kernel<<<grid, block>>>(x, clips, out, n);
}